// round 4
// baseline (speedup 1.0000x reference)
#include <cuda_runtime.h>
#include <cfloat>
#include <cstdint>

#define BSZ   8
#define NPTS  2048
#define KNN   10
#define MBIG  (NPTS * KNN)   // 20480

// ---------------- scratch (device globals; allocation-free) ----------------
__device__ float g_G   [(size_t)BSZ * NPTS * NPTS];     // gram
__device__ float g_sq  [BSZ * NPTS];
__device__ int   g_idx [BSZ * NPTS * KNN];
__device__ float g_feat[(size_t)BSZ * 362 * MBIG];      // edge features (max 2C=362)
__device__ float g_y1  [(size_t)BSZ * 430 * MBIG];      // conv1 out (max O=430)
__device__ float g_y2  [(size_t)BSZ * 512 * MBIG];      // conv2 out (max O=512)
__device__ float g_x1  [BSZ * 181 * NPTS];
__device__ float g_x2  [BSZ * 512 * NPTS];
__device__ float g_xc  [BSZ * 693 * NPTS];
__device__ float g_y3  [BSZ * 595 * NPTS];
__device__ float g_wt  [512 * 693];                     // transposed weights
__device__ float g_mean[1024];
__device__ float g_var [1024];

// ---- squared norms: emulate XLA row-reduction (lane-strided + shfl tree) ----
__global__ void sqnorm_warp_k(const float* __restrict__ X, float* __restrict__ sq, int C)
{
    int gw   = (blockIdx.x * blockDim.x + threadIdx.x) >> 5;   // warp id over B*N
    int lane = threadIdx.x & 31;
    if (gw >= BSZ * NPTS) return;
    int b = gw / NPTS, n = gw % NPTS;
    const float* Xb = X + (size_t)b * C * NPTS + n;
    float s = 0.f;
    for (int c = lane; c < C; c += 32) {
        float v = Xb[(size_t)c * NPTS];
        s = __fadd_rn(s, __fmul_rn(v, v));
    }
    #pragma unroll
    for (int off = 16; off > 0; off >>= 1)
        s = __fadd_rn(s, __shfl_down_sync(0xffffffffu, s, off));
    if (lane == 0) sq[gw] = s;
}

// ---------------- W transpose: Wt[c][o] = W[o][c] ----------------
__global__ void transw_k(const float* __restrict__ W, float* __restrict__ Wt, int O, int C)
{
    int i = blockIdx.x * blockDim.x + threadIdx.x;
    if (i >= O * C) return;
    int o = i % O, c = i / O;
    Wt[i] = W[(size_t)o * C + c];
}

// ---------------- 128x128x8 SIMT sgemm (fp32, single-acc ascending k) --------
__global__ __launch_bounds__(256) void gemm128_k(
    const float* __restrict__ Wt, const float* __restrict__ X,
    const float* __restrict__ bias,
    const float* __restrict__ bnm, const float* __restrict__ bnv,
    const float* __restrict__ bng, const float* __restrict__ bnb,
    float* __restrict__ Y, int O, int C, int M,
    size_t sW, size_t sX, size_t sY)
{
    const int b = blockIdx.z;
    const float* Wb = Wt + (size_t)b * sW;
    const float* Xb = X  + (size_t)b * sX;
    float* Yb = Y + (size_t)b * sY;
    const int m0 = blockIdx.x * 128;
    const int o0 = blockIdx.y * 128;
    const int tid = threadIdx.x;
    const int tx = tid & 15, ty = tid >> 4;

    __shared__ float As[8][128];   // [c][o]
    __shared__ float Bs[8][128];   // [c][m]

    float acc[2][2][4][4] = {};
    const bool bn = (bnm != nullptr);

    for (int c0 = 0; c0 < C; c0 += 8) {
        #pragma unroll
        for (int i = 0; i < 4; i++) {
            int idx = tid + i * 256;
            int kc = idx >> 7;
            int o  = idx & 127;
            int c  = c0 + kc;
            float v = 0.f;
            if (c < C && (o0 + o) < O) v = Wb[(size_t)c * O + o0 + o];
            As[kc][o] = v;
        }
        {
            int kc  = tid >> 5;
            int col = (tid & 31) * 4;
            int c   = c0 + kc;
            float4 v = make_float4(0.f, 0.f, 0.f, 0.f);
            if (c < C) {
                v = *reinterpret_cast<const float4*>(&Xb[(size_t)c * M + m0 + col]);
                if (bn) {
                    float a  = rsqrtf(bnv[c] + 1e-5f) * bng[c];
                    float bb = bnb[c] - bnm[c] * a;
                    float t;
                    t = fmaf(v.x, a, bb); v.x = (t >= 0.f) ? t : 0.2f * t;
                    t = fmaf(v.y, a, bb); v.y = (t >= 0.f) ? t : 0.2f * t;
                    t = fmaf(v.z, a, bb); v.z = (t >= 0.f) ? t : 0.2f * t;
                    t = fmaf(v.w, a, bb); v.w = (t >= 0.f) ? t : 0.2f * t;
                }
            }
            *reinterpret_cast<float4*>(&Bs[kc][col]) = v;
        }
        __syncthreads();
        #pragma unroll
        for (int k = 0; k < 8; k++) {
            float a[2][4], bb[2][4];
            *(float4*)a[0]  = *(const float4*)&As[k][ty * 4];
            *(float4*)a[1]  = *(const float4*)&As[k][64 + ty * 4];
            *(float4*)bb[0] = *(const float4*)&Bs[k][tx * 4];
            *(float4*)bb[1] = *(const float4*)&Bs[k][64 + tx * 4];
            #pragma unroll
            for (int rh = 0; rh < 2; rh++)
                #pragma unroll
                for (int ch = 0; ch < 2; ch++)
                    #pragma unroll
                    for (int i = 0; i < 4; i++)
                        #pragma unroll
                        for (int j = 0; j < 4; j++)
                            acc[rh][ch][i][j] = fmaf(a[rh][i], bb[ch][j], acc[rh][ch][i][j]);
        }
        __syncthreads();
    }
    #pragma unroll
    for (int rh = 0; rh < 2; rh++)
        #pragma unroll
        for (int i = 0; i < 4; i++) {
            int o = o0 + rh * 64 + ty * 4 + i;
            if (o < O) {
                if (bias) {
                    float bv = bias[o];
                    #pragma unroll
                    for (int ch = 0; ch < 2; ch++) {
                        float4 r;
                        r.x = acc[rh][ch][i][0] + bv;
                        r.y = acc[rh][ch][i][1] + bv;
                        r.z = acc[rh][ch][i][2] + bv;
                        r.w = acc[rh][ch][i][3] + bv;
                        *(float4*)&Yb[(size_t)o * M + m0 + ch * 64 + tx * 4] = r;
                    }
                } else {
                    #pragma unroll
                    for (int ch = 0; ch < 2; ch++) {
                        float4 r = make_float4(acc[rh][ch][i][0], acc[rh][ch][i][1],
                                               acc[rh][ch][i][2], acc[rh][ch][i][3]);
                        *(float4*)&Yb[(size_t)o * M + m0 + ch * 64 + tx * 4] = r;
                    }
                }
            }
        }
}

// ---------------- top-10 by fp32 key, JAX expression order -------------------
__global__ void topk_k(const float* __restrict__ G, const float* __restrict__ sq,
                       int* __restrict__ idx)
{
    const int n = blockIdx.x, b = blockIdx.y;
    const float* Gr  = G + ((size_t)b * NPTS + n) * NPTS;
    const float* sqb = sq + b * NPTS;
    __shared__ float key[NPTS];
    __shared__ float rv[256];
    __shared__ int   ri[256];
    const int t = threadIdx.x;
    const float sqn = sqb[n];
    for (int j = t; j < NPTS; j += 256)
        key[j] = (j == n) ? FLT_MAX
               : __fadd_rn(__fadd_rn(__fmul_rn(-2.f, Gr[j]), sqb[j]), sqn);
    __syncthreads();
    for (int s = 0; s < KNN; s++) {
        float bv = FLT_MAX; int bi = 0x7fffffff;
        for (int j = t; j < NPTS; j += 256) {
            float v = key[j];
            if (v < bv || (v == bv && j < bi)) { bv = v; bi = j; }
        }
        rv[t] = bv; ri[t] = bi;
        __syncthreads();
        for (int w = 128; w > 0; w >>= 1) {
            if (t < w) {
                float v2 = rv[t + w]; int i2 = ri[t + w];
                if (v2 < rv[t] || (v2 == rv[t] && i2 < ri[t])) { rv[t] = v2; ri[t] = i2; }
            }
            __syncthreads();
        }
        if (t == 0) {
            idx[((size_t)b * NPTS + n) * KNN + s] = ri[0];
            key[ri[0]] = FLT_MAX;
        }
        __syncthreads();
    }
}

// ---------------- gather edge features: F[b][2C][n*K+k] ----------------
__global__ void gather_k(const float* __restrict__ X, const int* __restrict__ idx,
                         float* __restrict__ F, int C)
{
    size_t total = (size_t)BSZ * 2 * C * MBIG;
    size_t i = (size_t)blockIdx.x * blockDim.x + threadIdx.x;
    if (i >= total) return;
    int m = (int)(i % MBIG);
    size_t r = i / MBIG;
    int c = (int)(r % (2 * C));
    int b = (int)(r / (2 * C));
    int n = m / KNN, k = m % KNN;
    if (c < C) {
        int j = idx[((size_t)b * NPTS + n) * KNN + k];
        const float* row = X + ((size_t)b * C + c) * NPTS;
        F[i] = row[j] - row[n];
    } else {
        F[i] = X[((size_t)b * C + (c - C)) * NPTS + n];
    }
}

// ---------------- BN statistics (two-pass, like jnp.mean / jnp.var) ----------
__global__ void bn_stats_k(const float* __restrict__ Y, float* __restrict__ mean,
                           float* __restrict__ var, int O, int M)
{
    const int c = blockIdx.x;
    const int t = threadIdx.x;
    __shared__ float ss[256];
    __shared__ float mu_s;
    float s = 0.f;
    for (int b = 0; b < BSZ; b++) {
        const float* p = Y + ((size_t)b * O + c) * M;
        for (int m = t; m < M; m += 256) s += p[m];
    }
    ss[t] = s;
    __syncthreads();
    for (int w = 128; w > 0; w >>= 1) {
        if (t < w) ss[t] += ss[t + w];
        __syncthreads();
    }
    if (t == 0) {
        float mu = ss[0] / ((float)BSZ * (float)M);
        mean[c] = mu;
        mu_s = mu;
    }
    __syncthreads();
    const float mu = mu_s;
    float s2 = 0.f;
    for (int b = 0; b < BSZ; b++) {
        const float* p = Y + ((size_t)b * O + c) * M;
        for (int m = t; m < M; m += 256) { float d = p[m] - mu; s2 += d * d; }
    }
    ss[t] = s2;
    __syncthreads();
    for (int w = 128; w > 0; w >>= 1) {
        if (t < w) ss[t] += ss[t + w];
        __syncthreads();
    }
    if (t == 0) var[c] = ss[0] / ((float)BSZ * (float)M);
}

// ---------------- apply BN affine + leaky relu, in place (output path) -------
__global__ void bn_leaky_k(float* __restrict__ Y, const float* __restrict__ mean,
                           const float* __restrict__ var, const float* __restrict__ gam,
                           const float* __restrict__ bet, int O, int M)
{
    size_t total = (size_t)BSZ * O * M;
    size_t i = (size_t)blockIdx.x * blockDim.x + threadIdx.x;
    if (i >= total) return;
    int c = (int)((i / M) % O);
    float a  = rsqrtf(var[c] + 1e-5f) * gam[c];
    float bb = bet[c] - mean[c] * a;
    float v = fmaf(Y[i], a, bb);
    Y[i] = (v >= 0.f) ? v : 0.2f * v;
}

// ---- BN + leaky + max over K, EXACT ref op order on the selected element ----
// bn-affine (a = g/s) is monotone: for g>=0, max_k f(y_k) = f(max_k y_k),
// for g<0, f(min_k y_k). Identical floats, 10x fewer exact divisions.
__global__ void bn_leaky_maxk_k(const float* __restrict__ Y, const float* __restrict__ mean,
                                const float* __restrict__ var, const float* __restrict__ gam,
                                const float* __restrict__ bet, float* __restrict__ out, int O)
{
    size_t total = (size_t)BSZ * O * NPTS;
    size_t i = (size_t)blockIdx.x * blockDim.x + threadIdx.x;
    if (i >= total) return;
    int n = (int)(i % NPTS);
    int c = (int)((i / NPTS) % O);
    int b = (int)(i / ((size_t)NPTS * O));
    const float mu = mean[c];
    const float s  = __fsqrt_rn(__fadd_rn(var[c], 1e-5f));
    const float g  = gam[c];
    const float be = bet[c];
    const float* p = Y + ((size_t)b * O + c) * MBIG + (size_t)n * KNN;
    float sel;
    if (g >= 0.f) {
        sel = p[0];
        #pragma unroll
        for (int k = 1; k < KNN; k++) sel = fmaxf(sel, p[k]);
    } else {
        sel = p[0];
        #pragma unroll
        for (int k = 1; k < KNN; k++) sel = fminf(sel, p[k]);
    }
    // ref: ((y - m) / sqrt(v+eps)) * g + be, each op separately rounded
    float t = __fdiv_rn(__fsub_rn(sel, mu), s);
    t = __fadd_rn(__fmul_rn(t, g), be);
    t = (t >= 0.f) ? t : __fmul_rn(0.2f, t);
    out[i] = t;
}

// ---------------- concat [x1;x2] -> xc [B][693][N] ----------------
__global__ void concat_k(const float* __restrict__ x1, const float* __restrict__ x2,
                         float* __restrict__ xc)
{
    size_t total = (size_t)BSZ * 693 * NPTS;
    size_t i = (size_t)blockIdx.x * blockDim.x + threadIdx.x;
    if (i >= total) return;
    int n = (int)(i % NPTS);
    int c = (int)((i / NPTS) % 693);
    int b = (int)(i / ((size_t)NPTS * 693));
    xc[i] = (c < 181) ? x1[((size_t)b * 181 + c) * NPTS + n]
                      : x2[((size_t)b * 512 + (c - 181)) * NPTS + n];
}

// ============================ host launcher ============================
static inline void* symaddr(const void* sym)
{
    void* p = nullptr;
    cudaGetSymbolAddress(&p, sym);
    return p;
}

extern "C" void kernel_launch(void* const* d_in, const int* in_sizes, int n_in,
                              void* d_out, int out_size)
{
    (void)in_sizes; (void)n_in; (void)out_size;
    const float* x = (const float*)d_in[0];

    const float* P[24];
    for (int i = 0; i < 24; i++) P[i] = (const float*)d_in[1 + i];
    #define W1(p)  P[(p)*8 + 0]
    #define B1(p)  P[(p)*8 + 1]
    #define G1(p)  P[(p)*8 + 2]
    #define BE1(p) P[(p)*8 + 3]
    #define W2(p)  P[(p)*8 + 4]
    #define B2(p)  P[(p)*8 + 5]
    #define G2(p)  P[(p)*8 + 6]
    #define BE2(p) P[(p)*8 + 7]

    float* G    = (float*)symaddr(g_G);
    float* SQ   = (float*)symaddr(g_sq);
    int*   IDX  = (int*)  symaddr(g_idx);
    float* FEAT = (float*)symaddr(g_feat);
    float* Y1   = (float*)symaddr(g_y1);
    float* Y2   = (float*)symaddr(g_y2);
    float* X1   = (float*)symaddr(g_x1);
    float* X2   = (float*)symaddr(g_x2);
    float* XC   = (float*)symaddr(g_xc);
    float* Y3   = (float*)symaddr(g_y3);
    float* WT   = (float*)symaddr(g_wt);
    float* MEAN = (float*)symaddr(g_mean);
    float* VAR  = (float*)symaddr(g_var);
    float* OUT  = (float*)d_out;

    const int ew = 256;
    #define GS(total) (unsigned)(((total) + ew - 1) / ew)

    auto conv = [&](const float* W, const float* bias, const float* Xin, float* Yout,
                    int O, int C, int M, bool fuse_bn, const float* gam, const float* bet) {
        transw_k<<<GS(O * C), ew>>>(W, WT, O, C);
        gemm128_k<<<dim3(M / 128, (O + 127) / 128, BSZ), 256>>>(
            WT, Xin, bias,
            fuse_bn ? MEAN : nullptr, fuse_bn ? VAR : nullptr,
            fuse_bn ? gam : nullptr,  fuse_bn ? bet : nullptr,
            Yout, O, C, M, 0, (size_t)C * M, (size_t)O * M);
    };

    auto graph_conv_block = [&](const float* xin, int C, int O1, int O2, int p,
                                float* xout) {
        // knn: sq via warp-tree (XLA row-reduction emulation), gram, topk
        sqnorm_warp_k<<<(BSZ * NPTS * 32 + 255) / 256, 256>>>(xin, SQ, C);
        gemm128_k<<<dim3(NPTS / 128, NPTS / 128, BSZ), 256>>>(
            xin, xin, nullptr, nullptr, nullptr, nullptr, nullptr,
            G, NPTS, C, NPTS,
            (size_t)C * NPTS, (size_t)C * NPTS, (size_t)NPTS * NPTS);
        topk_k<<<dim3(NPTS, BSZ), 256>>>(G, SQ, IDX);
        // edge features
        int twoC = 2 * C;
        gather_k<<<GS((size_t)BSZ * twoC * MBIG), ew>>>(xin, IDX, FEAT, C);
        // conv1 -> stats
        conv(W1(p), B1(p), FEAT, Y1, O1, twoC, MBIG, false, nullptr, nullptr);
        bn_stats_k<<<O1, 256>>>(Y1, MEAN, VAR, O1, MBIG);
        // conv2 with fused BN1+leaky on input -> stats -> BN2+leaky+maxk (exact)
        conv(W2(p), B2(p), Y1, Y2, O2, O1, MBIG, true, G1(p), BE1(p));
        bn_stats_k<<<O2, 256>>>(Y2, MEAN, VAR, O2, MBIG);
        bn_leaky_maxk_k<<<GS((size_t)BSZ * O2 * NPTS), ew>>>(Y2, MEAN, VAR, G2(p), BE2(p), xout, O2);
    };

    // block 1: C=64 -> 152 -> 181, pooled to X1
    graph_conv_block(x,  64, 152, 181, 0, X1);
    // block 2: C=181 -> 430 -> 512, pooled to X2
    graph_conv_block(X1, 181, 430, 512, 1, X2);

    // block 3: concat -> 595 -> 512 (no graph, no pooling)
    concat_k<<<GS((size_t)BSZ * 693 * NPTS), ew>>>(X1, X2, XC);
    conv(W1(2), B1(2), XC, Y3, 595, 693, NPTS, false, nullptr, nullptr);
    bn_stats_k<<<595, 256>>>(Y3, MEAN, VAR, 595, NPTS);
    conv(W2(2), B2(2), Y3, OUT, 512, 595, NPTS, true, G1(2), BE1(2));
    bn_stats_k<<<512, 256>>>(OUT, MEAN, VAR, 512, NPTS);
    bn_leaky_k<<<GS((size_t)BSZ * 512 * NPTS), ew>>>(OUT, MEAN, VAR, G2(2), BE2(2), 512, NPTS);
}

// round 6
// speedup vs baseline: 1.6120x; 1.6120x over previous
#include <cuda_runtime.h>
#include <cfloat>
#include <cstdint>

#define BSZ   8
#define NPTS  2048
#define KNN   10
#define MBIG  (NPTS * KNN)   // 20480
#define OPAD  768            // padded O stride for transposed weights
#define CPAD  704            // padded C rows

// ---------------- scratch (device globals; allocation-free) ----------------
__device__ float g_G   [(size_t)BSZ * NPTS * NPTS];     // gram
__device__ float g_sq  [BSZ * NPTS];
__device__ int   g_idx [BSZ * NPTS * KNN];
__device__ float g_feat[(size_t)BSZ * 362 * MBIG];      // edge features (max 2C=362)
__device__ float g_y1  [(size_t)BSZ * 430 * MBIG];      // conv1 out (max O=430)
__device__ float g_y2  [(size_t)BSZ * 512 * MBIG];      // conv2 out (max O=512)
__device__ float g_x1  [BSZ * 181 * NPTS];
__device__ float g_x2  [BSZ * 512 * NPTS];
__device__ float g_xc  [BSZ * 693 * NPTS];
__device__ float g_y3  [BSZ * 595 * NPTS];
__device__ float g_wt  [CPAD * OPAD];                   // transposed + padded weights
__device__ float g_mean[1024];
__device__ float g_var [1024];

// ---- squared norms: XLA row-reduction emulation (lane-strided + shfl tree) --
// BIT-FROZEN (feeds knn) — do not change.
__global__ void sqnorm_warp_k(const float* __restrict__ X, float* __restrict__ sq, int C)
{
    int gw   = (blockIdx.x * blockDim.x + threadIdx.x) >> 5;
    int lane = threadIdx.x & 31;
    if (gw >= BSZ * NPTS) return;
    int b = gw / NPTS, n = gw % NPTS;
    const float* Xb = X + (size_t)b * C * NPTS + n;
    float s = 0.f;
    for (int c = lane; c < C; c += 32) {
        float v = Xb[(size_t)c * NPTS];
        s = __fadd_rn(s, __fmul_rn(v, v));
    }
    #pragma unroll
    for (int off = 16; off > 0; off >>= 1)
        s = __fadd_rn(s, __shfl_down_sync(0xffffffffu, s, off));
    if (lane == 0) sq[gw] = s;
}

// ---------------- W transpose into padded buffer: Wt[c][o], zeros outside ----
__global__ void transw_k(const float* __restrict__ W, float* __restrict__ Wt, int O, int C)
{
    int i = blockIdx.x * blockDim.x + threadIdx.x;
    int ctot = (C + 7) & ~7;           // rows actually read by GEMM
    if (i >= ctot * OPAD) return;
    int c = i / OPAD, o = i % OPAD;
    Wt[i] = (c < C && o < O) ? W[(size_t)o * C + c] : 0.f;
}

// ---------------- cp.async helpers ----------------
__device__ __forceinline__ void cpa16(uint32_t s, const void* g, int sz)
{
    asm volatile("cp.async.cg.shared.global [%0], [%1], 16, %2;"
                 :: "r"(s), "l"(g), "r"(sz));
}
__device__ __forceinline__ void cpa_commit() { asm volatile("cp.async.commit_group;"); }
template<int N> __device__ __forceinline__ void cpa_wait()
{ asm volatile("cp.async.wait_group %0;" :: "n"(N)); }

// ------- double-buffered 128x128x8 SIMT sgemm (ascending-k single acc) -------
// Bit-identical accumulation order to the round-4 passing gemm.
__global__ __launch_bounds__(256, 2) void gemm_db_k(
    const float* __restrict__ A, const float* __restrict__ X,
    const float* __restrict__ bias, float* __restrict__ Y,
    int O, int C, int M, int ldA, size_t sA, size_t sX, size_t sY)
{
    const int b = blockIdx.z;
    const float* Ab = A + (size_t)b * sA;
    const float* Xb = X + (size_t)b * sX;
    float* Yb = Y + (size_t)b * sY;
    const int m0 = blockIdx.x * 128;
    const int o0 = blockIdx.y * 128;
    const int tid = threadIdx.x;
    const int tx = tid & 15, ty = tid >> 4;

    __shared__ float As[2][8][128];
    __shared__ float Bs[2][8][128];

    const int cc   = tid >> 5;        // 0..7: k-row this thread fills
    const int col4 = (tid & 31) * 4;  // 0..124

    uint32_t sa0 = (uint32_t)__cvta_generic_to_shared(&As[0][cc][col4]);
    uint32_t sb0 = (uint32_t)__cvta_generic_to_shared(&Bs[0][cc][col4]);
    const uint32_t bufoff = 8 * 128 * 4;

    const int ntiles = (C + 7) >> 3;

    float acc[2][2][4][4] = {};

    // prefetch tile 0
    {
        int c = cc;
        int pz = (c < C) ? 16 : 0;
        int cs = (c < C) ? c : 0;
        cpa16(sa0, Ab + (size_t)cs * ldA + o0 + col4, pz);
        cpa16(sb0, Xb + (size_t)cs * M + m0 + col4, pz);
        cpa_commit();
    }

    for (int it = 0; it < ntiles; it++) {
        int buf = it & 1;
        if (it + 1 < ntiles) {
            int c = (it + 1) * 8 + cc;
            int pz = (c < C) ? 16 : 0;
            int cs = (c < C) ? c : 0;
            uint32_t nb = ((it + 1) & 1) * bufoff;
            cpa16(sa0 + nb, Ab + (size_t)cs * ldA + o0 + col4, pz);
            cpa16(sb0 + nb, Xb + (size_t)cs * M + m0 + col4, pz);
            cpa_commit();
            cpa_wait<1>();
        } else {
            cpa_wait<0>();
        }
        __syncthreads();
        #pragma unroll
        for (int k = 0; k < 8; k++) {
            float a[2][4], x[2][4];
            *(float4*)a[0] = *(const float4*)&As[buf][k][ty * 4];
            *(float4*)a[1] = *(const float4*)&As[buf][k][64 + ty * 4];
            *(float4*)x[0] = *(const float4*)&Bs[buf][k][tx * 4];
            *(float4*)x[1] = *(const float4*)&Bs[buf][k][64 + tx * 4];
            #pragma unroll
            for (int rh = 0; rh < 2; rh++)
                #pragma unroll
                for (int ch = 0; ch < 2; ch++)
                    #pragma unroll
                    for (int i = 0; i < 4; i++)
                        #pragma unroll
                        for (int j = 0; j < 4; j++)
                            acc[rh][ch][i][j] = fmaf(a[rh][i], x[ch][j], acc[rh][ch][i][j]);
        }
        __syncthreads();
    }

    #pragma unroll
    for (int rh = 0; rh < 2; rh++)
        #pragma unroll
        for (int i = 0; i < 4; i++) {
            int o = o0 + rh * 64 + ty * 4 + i;
            if (o < O) {
                if (bias) {
                    float bv = bias[o];
                    #pragma unroll
                    for (int ch = 0; ch < 2; ch++) {
                        float4 r;
                        r.x = acc[rh][ch][i][0] + bv;
                        r.y = acc[rh][ch][i][1] + bv;
                        r.z = acc[rh][ch][i][2] + bv;
                        r.w = acc[rh][ch][i][3] + bv;
                        *(float4*)&Yb[(size_t)o * M + m0 + ch * 64 + tx * 4] = r;
                    }
                } else {
                    #pragma unroll
                    for (int ch = 0; ch < 2; ch++) {
                        float4 r = make_float4(acc[rh][ch][i][0], acc[rh][ch][i][1],
                                               acc[rh][ch][i][2], acc[rh][ch][i][3]);
                        *(float4*)&Yb[(size_t)o * M + m0 + ch * 64 + tx * 4] = r;
                    }
                }
            }
        }
}

// ---------------- top-10, EXACT round-4 version (BIT-FROZEN) ----------------
__global__ void topk_k(const float* __restrict__ G, const float* __restrict__ sq,
                       int* __restrict__ idx)
{
    const int n = blockIdx.x, b = blockIdx.y;
    const float* Gr  = G + ((size_t)b * NPTS + n) * NPTS;
    const float* sqb = sq + b * NPTS;
    __shared__ float key[NPTS];
    __shared__ float rv[256];
    __shared__ int   ri[256];
    const int t = threadIdx.x;
    const float sqn = sqb[n];
    for (int j = t; j < NPTS; j += 256)
        key[j] = (j == n) ? FLT_MAX
               : __fadd_rn(__fadd_rn(__fmul_rn(-2.f, Gr[j]), sqb[j]), sqn);
    __syncthreads();
    for (int s = 0; s < KNN; s++) {
        float bv = FLT_MAX; int bi = 0x7fffffff;
        for (int j = t; j < NPTS; j += 256) {
            float v = key[j];
            if (v < bv || (v == bv && j < bi)) { bv = v; bi = j; }
        }
        rv[t] = bv; ri[t] = bi;
        __syncthreads();
        for (int w = 128; w > 0; w >>= 1) {
            if (t < w) {
                float v2 = rv[t + w]; int i2 = ri[t + w];
                if (v2 < rv[t] || (v2 == rv[t] && i2 < ri[t])) { rv[t] = v2; ri[t] = i2; }
            }
            __syncthreads();
        }
        if (t == 0) {
            idx[((size_t)b * NPTS + n) * KNN + s] = ri[0];
            key[ri[0]] = FLT_MAX;
        }
        __syncthreads();
    }
}

// ---------------- gather edge features: F[b][2C][n*K+k] ----------------
__global__ void gather_k(const float* __restrict__ X, const int* __restrict__ idx,
                         float* __restrict__ F, int C)
{
    size_t total = (size_t)BSZ * 2 * C * MBIG;
    size_t i = (size_t)blockIdx.x * blockDim.x + threadIdx.x;
    if (i >= total) return;
    int m = (int)(i % MBIG);
    size_t r = i / MBIG;
    int c = (int)(r % (2 * C));
    int b = (int)(r / (2 * C));
    int n = m / KNN, k = m % KNN;
    if (c < C) {
        int j = idx[((size_t)b * NPTS + n) * KNN + k];
        const float* row = X + ((size_t)b * C + c) * NPTS;
        F[i] = row[j] - row[n];
    } else {
        F[i] = X[((size_t)b * C + (c - C)) * NPTS + n];
    }
}

// ------- BN statistics, EXACT round-4 version (BIT-FROZEN: feeds knn-2) ------
__global__ void bn_stats_k(const float* __restrict__ Y, float* __restrict__ mean,
                           float* __restrict__ var, int O, int M)
{
    const int c = blockIdx.x;
    const int t = threadIdx.x;
    __shared__ float ss[256];
    __shared__ float mu_s;
    float s = 0.f;
    for (int b = 0; b < BSZ; b++) {
        const float* p = Y + ((size_t)b * O + c) * M;
        for (int m = t; m < M; m += 256) s += p[m];
    }
    ss[t] = s;
    __syncthreads();
    for (int w = 128; w > 0; w >>= 1) {
        if (t < w) ss[t] += ss[t + w];
        __syncthreads();
    }
    if (t == 0) {
        float mu = ss[0] / ((float)BSZ * (float)M);
        mean[c] = mu;
        mu_s = mu;
    }
    __syncthreads();
    const float mu = mu_s;
    float s2 = 0.f;
    for (int b = 0; b < BSZ; b++) {
        const float* p = Y + ((size_t)b * O + c) * M;
        for (int m = t; m < M; m += 256) { float d = p[m] - mu; s2 += d * d; }
    }
    ss[t] = s2;
    __syncthreads();
    for (int w = 128; w > 0; w >>= 1) {
        if (t < w) ss[t] += ss[t + w];
        __syncthreads();
    }
    if (t == 0) var[c] = ss[0] / ((float)BSZ * (float)M);
}

// -------- apply BN affine + leaky relu, in place (bit-identical per elem) ----
__global__ void bn_leaky_k(float* __restrict__ Y, const float* __restrict__ mean,
                           const float* __restrict__ var, const float* __restrict__ gam,
                           const float* __restrict__ bet, int O, size_t M)
{
    size_t total = (size_t)BSZ * O * M;
    size_t i = ((size_t)blockIdx.x * blockDim.x + threadIdx.x) * 4;
    if (i >= total) return;
    int c = (int)((i / M) % O);
    float a  = rsqrtf(var[c] + 1e-5f) * gam[c];
    float bb = bet[c] - mean[c] * a;
    float4 v = *(float4*)(Y + i);
    float tt;
    tt = fmaf(v.x, a, bb); v.x = (tt >= 0.f) ? tt : 0.2f * tt;
    tt = fmaf(v.y, a, bb); v.y = (tt >= 0.f) ? tt : 0.2f * tt;
    tt = fmaf(v.z, a, bb); v.z = (tt >= 0.f) ? tt : 0.2f * tt;
    tt = fmaf(v.w, a, bb); v.w = (tt >= 0.f) ? tt : 0.2f * tt;
    *(float4*)(Y + i) = v;
}

// ---- BN + leaky + max over K, exact ref op order (BIT-FROZEN) ----
__global__ void bn_leaky_maxk_k(const float* __restrict__ Y, const float* __restrict__ mean,
                                const float* __restrict__ var, const float* __restrict__ gam,
                                const float* __restrict__ bet, float* __restrict__ out, int O)
{
    size_t total = (size_t)BSZ * O * NPTS;
    size_t i = (size_t)blockIdx.x * blockDim.x + threadIdx.x;
    if (i >= total) return;
    int n = (int)(i % NPTS);
    int c = (int)((i / NPTS) % O);
    int b = (int)(i / ((size_t)NPTS * O));
    const float mu = mean[c];
    const float s  = __fsqrt_rn(__fadd_rn(var[c], 1e-5f));
    const float g  = gam[c];
    const float be = bet[c];
    const float* p = Y + ((size_t)b * O + c) * MBIG + (size_t)n * KNN;
    float sel = p[0];
    if (g >= 0.f) {
        #pragma unroll
        for (int k = 1; k < KNN; k++) sel = fmaxf(sel, p[k]);
    } else {
        #pragma unroll
        for (int k = 1; k < KNN; k++) sel = fminf(sel, p[k]);
    }
    float t = __fdiv_rn(__fsub_rn(sel, mu), s);
    t = __fadd_rn(__fmul_rn(t, g), be);
    t = (t >= 0.f) ? t : __fmul_rn(0.2f, t);
    out[i] = t;
}

// ---------------- concat [x1;x2] -> xc [B][693][N] ----------------
__global__ void concat_k(const float* __restrict__ x1, const float* __restrict__ x2,
                         float* __restrict__ xc)
{
    size_t total = (size_t)BSZ * 693 * NPTS;
    size_t i = (size_t)blockIdx.x * blockDim.x + threadIdx.x;
    if (i >= total) return;
    int n = (int)(i % NPTS);
    int c = (int)((i / NPTS) % 693);
    int b = (int)(i / ((size_t)NPTS * 693));
    xc[i] = (c < 181) ? x1[((size_t)b * 181 + c) * NPTS + n]
                      : x2[((size_t)b * 512 + (c - 181)) * NPTS + n];
}

// ============================ host launcher ============================
static inline void* symaddr(const void* sym)
{
    void* p = nullptr;
    cudaGetSymbolAddress(&p, sym);
    return p;
}

extern "C" void kernel_launch(void* const* d_in, const int* in_sizes, int n_in,
                              void* d_out, int out_size)
{
    (void)in_sizes; (void)n_in; (void)out_size;
    const float* x = (const float*)d_in[0];

    const float* P[24];
    for (int i = 0; i < 24; i++) P[i] = (const float*)d_in[1 + i];
    #define W1(p)  P[(p)*8 + 0]
    #define B1(p)  P[(p)*8 + 1]
    #define G1(p)  P[(p)*8 + 2]
    #define BE1(p) P[(p)*8 + 3]
    #define W2(p)  P[(p)*8 + 4]
    #define B2(p)  P[(p)*8 + 5]
    #define G2(p)  P[(p)*8 + 6]
    #define BE2(p) P[(p)*8 + 7]

    float* G    = (float*)symaddr(g_G);
    float* SQ   = (float*)symaddr(g_sq);
    int*   IDX  = (int*)  symaddr(g_idx);
    float* FEAT = (float*)symaddr(g_feat);
    float* Y1   = (float*)symaddr(g_y1);
    float* Y2   = (float*)symaddr(g_y2);
    float* X1   = (float*)symaddr(g_x1);
    float* X2   = (float*)symaddr(g_x2);
    float* XC   = (float*)symaddr(g_xc);
    float* Y3   = (float*)symaddr(g_y3);
    float* WT   = (float*)symaddr(g_wt);
    float* MEAN = (float*)symaddr(g_mean);
    float* VAR  = (float*)symaddr(g_var);
    float* OUT  = (float*)d_out;

    const int ew = 256;
    #define GS(total) (unsigned)(((total) + ew - 1) / ew)

    auto conv = [&](const float* W, const float* bias, const float* Xin, float* Yout,
                    int O, int C, int M) {
        int ctot = (C + 7) & ~7;
        transw_k<<<GS(ctot * OPAD), ew>>>(W, WT, O, C);
        gemm_db_k<<<dim3(M / 128, (O + 127) / 128, BSZ), 256>>>(
            WT, Xin, bias, Yout, O, C, M, OPAD, 0, (size_t)C * M, (size_t)O * M);
    };

    auto graph_conv_block = [&](const float* xin, int C, int O1, int O2, int p,
                                float* xout) {
        // knn: sq (warp tree), gram (double-buffered gemm), topk
        sqnorm_warp_k<<<(BSZ * NPTS * 32 + 255) / 256, 256>>>(xin, SQ, C);
        gemm_db_k<<<dim3(NPTS / 128, NPTS / 128, BSZ), 256>>>(
            xin, xin, nullptr, G, NPTS, C, NPTS,
            NPTS, (size_t)C * NPTS, (size_t)C * NPTS, (size_t)NPTS * NPTS);
        topk_k<<<dim3(NPTS, BSZ), 256>>>(G, SQ, IDX);
        // edge features
        int twoC = 2 * C;
        gather_k<<<GS((size_t)BSZ * twoC * MBIG), ew>>>(xin, IDX, FEAT, C);
        // conv1 -> stats -> bn+leaky (in place)
        conv(W1(p), B1(p), FEAT, Y1, O1, twoC, MBIG);
        bn_stats_k<<<O1, 256>>>(Y1, MEAN, VAR, O1, MBIG);
        bn_leaky_k<<<GS((size_t)BSZ * O1 * MBIG / 4), ew>>>(Y1, MEAN, VAR, G1(p), BE1(p), O1, MBIG);
        // conv2 -> stats -> BN2+leaky+maxk (exact ref order)
        conv(W2(p), B2(p), Y1, Y2, O2, O1, MBIG);
        bn_stats_k<<<O2, 256>>>(Y2, MEAN, VAR, O2, MBIG);
        bn_leaky_maxk_k<<<GS((size_t)BSZ * O2 * NPTS), ew>>>(Y2, MEAN, VAR, G2(p), BE2(p), xout, O2);
    };

    // block 1: C=64 -> 152 -> 181, pooled to X1
    graph_conv_block(x,  64, 152, 181, 0, X1);
    // block 2: C=181 -> 430 -> 512, pooled to X2
    graph_conv_block(X1, 181, 430, 512, 1, X2);

    // block 3: concat -> 595 -> 512 (no graph, no pooling)
    concat_k<<<GS((size_t)BSZ * 693 * NPTS), ew>>>(X1, X2, XC);
    conv(W1(2), B1(2), XC, Y3, 595, 693, NPTS);
    bn_stats_k<<<595, 256>>>(Y3, MEAN, VAR, 595, NPTS);
    bn_leaky_k<<<GS((size_t)BSZ * 595 * NPTS / 4), ew>>>(Y3, MEAN, VAR, G1(2), BE1(2), 595, NPTS);
    conv(W2(2), B2(2), Y3, OUT, 512, 595, NPTS);
    bn_stats_k<<<512, 256>>>(OUT, MEAN, VAR, 512, NPTS);
    bn_leaky_k<<<GS((size_t)BSZ * 512 * NPTS / 4), ew>>>(OUT, MEAN, VAR, G2(2), BE2(2), 512, NPTS);
}

// round 7
// speedup vs baseline: 1.8920x; 1.1737x over previous
#include <cuda_runtime.h>
#include <cfloat>
#include <cstdint>

#define BSZ   8
#define NPTS  2048
#define KNN   10
#define MBIG  (NPTS * KNN)   // 20480
#define OPAD  768            // padded O stride for transposed weights
#define CPAD  704            // padded C rows

typedef unsigned long long u64;
union F2U { float2 f2; u64 u; };

// ---------------- scratch (device globals; allocation-free) ----------------
__device__ float g_G   [(size_t)BSZ * NPTS * NPTS];     // gram
__device__ float g_sq  [BSZ * NPTS];
__device__ int   g_idx [BSZ * NPTS * KNN];
__device__ float g_feat[(size_t)BSZ * 362 * MBIG];      // edge features (max 2C=362)
__device__ float g_y1  [(size_t)BSZ * 430 * MBIG];      // conv1 out (max O=430)
__device__ float g_y2  [(size_t)BSZ * 512 * MBIG];      // conv2 out (max O=512)
__device__ float g_x1  [BSZ * 181 * NPTS];
__device__ float g_x2  [BSZ * 512 * NPTS];
__device__ float g_xc  [BSZ * 693 * NPTS];
__device__ float g_y3  [BSZ * 595 * NPTS];
__device__ float g_wt  [CPAD * OPAD];                   // transposed + padded weights
__device__ float g_mean[1024];
__device__ float g_var [1024];

// ---- squared norms: XLA row-reduction emulation (BIT-FROZEN, feeds knn) ----
__global__ void sqnorm_warp_k(const float* __restrict__ X, float* __restrict__ sq, int C)
{
    int gw   = (blockIdx.x * blockDim.x + threadIdx.x) >> 5;
    int lane = threadIdx.x & 31;
    if (gw >= BSZ * NPTS) return;
    int b = gw / NPTS, n = gw % NPTS;
    const float* Xb = X + (size_t)b * C * NPTS + n;
    float s = 0.f;
    for (int c = lane; c < C; c += 32) {
        float v = Xb[(size_t)c * NPTS];
        s = __fadd_rn(s, __fmul_rn(v, v));
    }
    #pragma unroll
    for (int off = 16; off > 0; off >>= 1)
        s = __fadd_rn(s, __shfl_down_sync(0xffffffffu, s, off));
    if (lane == 0) sq[gw] = s;
}

// ---------------- W transpose into padded buffer: Wt[c][o], zeros outside ----
__global__ void transw_k(const float* __restrict__ W, float* __restrict__ Wt, int O, int C)
{
    int i = blockIdx.x * blockDim.x + threadIdx.x;
    int ctot = (C + 7) & ~7;
    if (i >= ctot * OPAD) return;
    int c = i / OPAD, o = i % OPAD;
    Wt[i] = (c < C && o < O) ? W[(size_t)o * C + c] : 0.f;
}

// ---------------- cp.async helpers ----------------
__device__ __forceinline__ void cpa16(uint32_t s, const void* g, int sz)
{
    asm volatile("cp.async.cg.shared.global [%0], [%1], 16, %2;"
                 :: "r"(s), "l"(g), "r"(sz));
}
__device__ __forceinline__ void cpa_commit() { asm volatile("cp.async.commit_group;"); }
template<int N> __device__ __forceinline__ void cpa_wait()
{ asm volatile("cp.async.wait_group %0;" :: "n"(N)); }

// packed dual fp32 FMA: d = a*b + d per 32-bit half (each half IEEE fp32 RN,
// identical rounding to scalar FFMA -> bit-identical accumulation chains)
__device__ __forceinline__ void ffma2(u64& d, u64 a, u64 b)
{
    asm("fma.rn.f32x2 %0, %1, %2, %0;" : "+l"(d) : "l"(a), "l"(b));
}
__device__ __forceinline__ u64 packdup(float a)
{
    u64 r;
    asm("mov.b64 %0, {%1, %1};" : "=l"(r) : "f"(a));
    return r;
}

// ------- double-buffered 128x128x8 SIMT sgemm, FFMA2 inner ------------------
// Bit-identical per-output accumulation to the round-4/6 passing gemms.
__global__ __launch_bounds__(256, 2) void gemm_db_k(
    const float* __restrict__ A, const float* __restrict__ X,
    const float* __restrict__ bias, float* __restrict__ Y,
    int O, int C, int M, int ldA, size_t sA, size_t sX, size_t sY)
{
    const int b = blockIdx.z;
    const float* Ab = A + (size_t)b * sA;
    const float* Xb = X + (size_t)b * sX;
    float* Yb = Y + (size_t)b * sY;
    const int m0 = blockIdx.x * 128;
    const int o0 = blockIdx.y * 128;
    const int tid = threadIdx.x;
    const int tx = tid & 15, ty = tid >> 4;

    __shared__ float As[2][8][128];
    __shared__ float Bs[2][8][128];

    const int cc   = tid >> 5;
    const int col4 = (tid & 31) * 4;

    uint32_t sa0 = (uint32_t)__cvta_generic_to_shared(&As[0][cc][col4]);
    uint32_t sb0 = (uint32_t)__cvta_generic_to_shared(&Bs[0][cc][col4]);
    const uint32_t bufoff = 8 * 128 * 4;

    const int ntiles = (C + 7) >> 3;

    u64 acc2[2][2][4][2];   // [rh][ch][i][jp], each holds m-pair (2j, 2j+1)
    #pragma unroll
    for (int rh = 0; rh < 2; rh++)
        #pragma unroll
        for (int ch = 0; ch < 2; ch++)
            #pragma unroll
            for (int i = 0; i < 4; i++)
                { acc2[rh][ch][i][0] = 0ull; acc2[rh][ch][i][1] = 0ull; }

    // prefetch tile 0
    {
        int c = cc;
        int pz = (c < C) ? 16 : 0;
        int cs = (c < C) ? c : 0;
        cpa16(sa0, Ab + (size_t)cs * ldA + o0 + col4, pz);
        cpa16(sb0, Xb + (size_t)cs * M + m0 + col4, pz);
        cpa_commit();
    }

    for (int it = 0; it < ntiles; it++) {
        int buf = it & 1;
        if (it + 1 < ntiles) {
            int c = (it + 1) * 8 + cc;
            int pz = (c < C) ? 16 : 0;
            int cs = (c < C) ? c : 0;
            uint32_t nb = ((it + 1) & 1) * bufoff;
            cpa16(sa0 + nb, Ab + (size_t)cs * ldA + o0 + col4, pz);
            cpa16(sb0 + nb, Xb + (size_t)cs * M + m0 + col4, pz);
            cpa_commit();
            cpa_wait<1>();
        } else {
            cpa_wait<0>();
        }
        __syncthreads();
        #pragma unroll
        for (int k = 0; k < 8; k++) {
            float a[2][4];
            *(float4*)a[0] = *(const float4*)&As[buf][k][ty * 4];
            *(float4*)a[1] = *(const float4*)&As[buf][k][64 + ty * 4];
            u64 x0[2], x1[2];
            {
                ulonglong2 v = *(const ulonglong2*)&Bs[buf][k][tx * 4];
                x0[0] = v.x; x0[1] = v.y;
            }
            {
                ulonglong2 v = *(const ulonglong2*)&Bs[buf][k][64 + tx * 4];
                x1[0] = v.x; x1[1] = v.y;
            }
            #pragma unroll
            for (int rh = 0; rh < 2; rh++)
                #pragma unroll
                for (int i = 0; i < 4; i++) {
                    u64 aa = packdup(a[rh][i]);
                    ffma2(acc2[rh][0][i][0], aa, x0[0]);
                    ffma2(acc2[rh][0][i][1], aa, x0[1]);
                    ffma2(acc2[rh][1][i][0], aa, x1[0]);
                    ffma2(acc2[rh][1][i][1], aa, x1[1]);
                }
        }
        __syncthreads();
    }

    #pragma unroll
    for (int rh = 0; rh < 2; rh++)
        #pragma unroll
        for (int i = 0; i < 4; i++) {
            int o = o0 + rh * 64 + ty * 4 + i;
            if (o < O) {
                #pragma unroll
                for (int ch = 0; ch < 2; ch++) {
                    F2U q0, q1;
                    q0.u = acc2[rh][ch][i][0];
                    q1.u = acc2[rh][ch][i][1];
                    float4 r;
                    if (bias) {
                        float bv = bias[o];
                        r.x = q0.f2.x + bv; r.y = q0.f2.y + bv;
                        r.z = q1.f2.x + bv; r.w = q1.f2.y + bv;
                    } else {
                        r.x = q0.f2.x; r.y = q0.f2.y;
                        r.z = q1.f2.x; r.w = q1.f2.y;
                    }
                    *(float4*)&Yb[(size_t)o * M + m0 + ch * 64 + tx * 4] = r;
                }
            }
        }
}

// ------- top-10: register-resident keys (selection-equivalent to frozen) -----
__global__ void topk_k(const float* __restrict__ G, const float* __restrict__ sq,
                       int* __restrict__ idx)
{
    const int n = blockIdx.x, b = blockIdx.y;
    const float* Gr  = G + ((size_t)b * NPTS + n) * NPTS;
    const float* sqb = sq + b * NPTS;
    const int t = threadIdx.x;
    const int lane = t & 31, warp = t >> 5;
    const float sqn = sqb[n];

    float key[8];
    #pragma unroll
    for (int s = 0; s < 8; s++) {
        int j = s * 256 + t;
        key[s] = (j == n) ? FLT_MAX
               : __fadd_rn(__fadd_rn(__fmul_rn(-2.f, Gr[j]), sqb[j]), sqn);
    }

    __shared__ float swv[8];
    __shared__ int   swi[8];
    __shared__ int   win;

    for (int r = 0; r < KNN; r++) {
        float bv = key[0]; int bs = 0;
        #pragma unroll
        for (int s = 1; s < 8; s++)
            if (key[s] < bv) { bv = key[s]; bs = s; }
        int bj = bs * 256 + t;
        #pragma unroll
        for (int off = 16; off > 0; off >>= 1) {
            float ov = __shfl_down_sync(0xffffffffu, bv, off);
            int   oj = __shfl_down_sync(0xffffffffu, bj, off);
            if (ov < bv || (ov == bv && oj < bj)) { bv = ov; bj = oj; }
        }
        if (lane == 0) { swv[warp] = bv; swi[warp] = bj; }
        __syncthreads();
        if (t == 0) {
            float fv = swv[0]; int fj = swi[0];
            #pragma unroll
            for (int w = 1; w < 8; w++)
                if (swv[w] < fv || (swv[w] == fv && swi[w] < fj)) { fv = swv[w]; fj = swi[w]; }
            idx[((size_t)b * NPTS + n) * KNN + r] = fj;
            win = fj;
        }
        __syncthreads();
        int fj = win;
        if ((fj & 255) == t) key[fj >> 8] = FLT_MAX;
        __syncthreads();
    }
}

// ---------------- gather edge features: F[b][2C][n*K+k] ----------------
__global__ void gather_k(const float* __restrict__ X, const int* __restrict__ idx,
                         float* __restrict__ F, int C)
{
    size_t total = (size_t)BSZ * 2 * C * MBIG;
    size_t i = (size_t)blockIdx.x * blockDim.x + threadIdx.x;
    if (i >= total) return;
    int m = (int)(i % MBIG);
    size_t r = i / MBIG;
    int c = (int)(r % (2 * C));
    int b = (int)(r / (2 * C));
    int n = m / KNN, k = m % KNN;
    if (c < C) {
        int j = idx[((size_t)b * NPTS + n) * KNN + k];
        const float* row = X + ((size_t)b * C + c) * NPTS;
        F[i] = row[j] - row[n];
    } else {
        F[i] = X[((size_t)b * C + (c - C)) * NPTS + n];
    }
}

// ------- BN statistics, two-pass (BIT-FROZEN: block-1 stats feed knn-2) ------
__global__ void bn_stats_k(const float* __restrict__ Y, float* __restrict__ mean,
                           float* __restrict__ var, int O, int M)
{
    const int c = blockIdx.x;
    const int t = threadIdx.x;
    __shared__ float ss[256];
    __shared__ float mu_s;
    float s = 0.f;
    for (int b = 0; b < BSZ; b++) {
        const float* p = Y + ((size_t)b * O + c) * M;
        for (int m = t; m < M; m += 256) s += p[m];
    }
    ss[t] = s;
    __syncthreads();
    for (int w = 128; w > 0; w >>= 1) {
        if (t < w) ss[t] += ss[t + w];
        __syncthreads();
    }
    if (t == 0) {
        float mu = ss[0] / ((float)BSZ * (float)M);
        mean[c] = mu;
        mu_s = mu;
    }
    __syncthreads();
    const float mu = mu_s;
    float s2 = 0.f;
    for (int b = 0; b < BSZ; b++) {
        const float* p = Y + ((size_t)b * O + c) * M;
        for (int m = t; m < M; m += 256) { float d = p[m] - mu; s2 += d * d; }
    }
    ss[t] = s2;
    __syncthreads();
    for (int w = 128; w > 0; w >>= 1) {
        if (t < w) ss[t] += ss[t + w];
        __syncthreads();
    }
    if (t == 0) var[c] = ss[0] / ((float)BSZ * (float)M);
}

// ------- BN statistics, single-pass (tolerance paths only: blocks 2 & 3) -----
__global__ void bn_stats_fast_k(const float* __restrict__ Y, float* __restrict__ mean,
                                float* __restrict__ var, int O, int M)
{
    const int c = blockIdx.x;
    const int t = threadIdx.x;
    __shared__ float ss[256], ss2[256];
    float s = 0.f, s2 = 0.f;
    for (int b = 0; b < BSZ; b++) {
        const float* p = Y + ((size_t)b * O + c) * M;
        for (int m = t * 4; m < M; m += 1024) {
            float4 v = *(const float4*)(p + m);
            s += v.x; s2 = fmaf(v.x, v.x, s2);
            s += v.y; s2 = fmaf(v.y, v.y, s2);
            s += v.z; s2 = fmaf(v.z, v.z, s2);
            s += v.w; s2 = fmaf(v.w, v.w, s2);
        }
    }
    ss[t] = s; ss2[t] = s2;
    __syncthreads();
    for (int w = 128; w > 0; w >>= 1) {
        if (t < w) { ss[t] += ss[t + w]; ss2[t] += ss2[t + w]; }
        __syncthreads();
    }
    if (t == 0) {
        float inv = 1.f / ((float)BSZ * (float)M);
        float mu  = ss[0] * inv;
        mean[c] = mu;
        var[c]  = fmaxf(ss2[0] * inv - mu * mu, 0.f);
    }
}

// -------- apply BN affine + leaky relu, in place ----
__global__ void bn_leaky_k(float* __restrict__ Y, const float* __restrict__ mean,
                           const float* __restrict__ var, const float* __restrict__ gam,
                           const float* __restrict__ bet, int O, size_t M)
{
    size_t total = (size_t)BSZ * O * M;
    size_t i = ((size_t)blockIdx.x * blockDim.x + threadIdx.x) * 4;
    if (i >= total) return;
    int c = (int)((i / M) % O);
    float a  = rsqrtf(var[c] + 1e-5f) * gam[c];
    float bb = bet[c] - mean[c] * a;
    float4 v = *(float4*)(Y + i);
    float tt;
    tt = fmaf(v.x, a, bb); v.x = (tt >= 0.f) ? tt : 0.2f * tt;
    tt = fmaf(v.y, a, bb); v.y = (tt >= 0.f) ? tt : 0.2f * tt;
    tt = fmaf(v.z, a, bb); v.z = (tt >= 0.f) ? tt : 0.2f * tt;
    tt = fmaf(v.w, a, bb); v.w = (tt >= 0.f) ? tt : 0.2f * tt;
    *(float4*)(Y + i) = v;
}

// ---- BN + leaky + max over K, exact ref op order (BIT-FROZEN) ----
__global__ void bn_leaky_maxk_k(const float* __restrict__ Y, const float* __restrict__ mean,
                                const float* __restrict__ var, const float* __restrict__ gam,
                                const float* __restrict__ bet, float* __restrict__ out, int O)
{
    size_t total = (size_t)BSZ * O * NPTS;
    size_t i = (size_t)blockIdx.x * blockDim.x + threadIdx.x;
    if (i >= total) return;
    int n = (int)(i % NPTS);
    int c = (int)((i / NPTS) % O);
    int b = (int)(i / ((size_t)NPTS * O));
    const float mu = mean[c];
    const float s  = __fsqrt_rn(__fadd_rn(var[c], 1e-5f));
    const float g  = gam[c];
    const float be = bet[c];
    const float* p = Y + ((size_t)b * O + c) * MBIG + (size_t)n * KNN;
    float sel = p[0];
    if (g >= 0.f) {
        #pragma unroll
        for (int k = 1; k < KNN; k++) sel = fmaxf(sel, p[k]);
    } else {
        #pragma unroll
        for (int k = 1; k < KNN; k++) sel = fminf(sel, p[k]);
    }
    float t = __fdiv_rn(__fsub_rn(sel, mu), s);
    t = __fadd_rn(__fmul_rn(t, g), be);
    t = (t >= 0.f) ? t : __fmul_rn(0.2f, t);
    out[i] = t;
}

// ---------------- concat [x1;x2] -> xc [B][693][N] ----------------
__global__ void concat_k(const float* __restrict__ x1, const float* __restrict__ x2,
                         float* __restrict__ xc)
{
    size_t total = (size_t)BSZ * 693 * NPTS;
    size_t i = (size_t)blockIdx.x * blockDim.x + threadIdx.x;
    if (i >= total) return;
    int n = (int)(i % NPTS);
    int c = (int)((i / NPTS) % 693);
    int b = (int)(i / ((size_t)NPTS * 693));
    xc[i] = (c < 181) ? x1[((size_t)b * 181 + c) * NPTS + n]
                      : x2[((size_t)b * 512 + (c - 181)) * NPTS + n];
}

// ============================ host launcher ============================
static inline void* symaddr(const void* sym)
{
    void* p = nullptr;
    cudaGetSymbolAddress(&p, sym);
    return p;
}

extern "C" void kernel_launch(void* const* d_in, const int* in_sizes, int n_in,
                              void* d_out, int out_size)
{
    (void)in_sizes; (void)n_in; (void)out_size;
    const float* x = (const float*)d_in[0];

    const float* P[24];
    for (int i = 0; i < 24; i++) P[i] = (const float*)d_in[1 + i];
    #define W1(p)  P[(p)*8 + 0]
    #define B1(p)  P[(p)*8 + 1]
    #define G1(p)  P[(p)*8 + 2]
    #define BE1(p) P[(p)*8 + 3]
    #define W2(p)  P[(p)*8 + 4]
    #define B2(p)  P[(p)*8 + 5]
    #define G2(p)  P[(p)*8 + 6]
    #define BE2(p) P[(p)*8 + 7]

    float* G    = (float*)symaddr(g_G);
    float* SQ   = (float*)symaddr(g_sq);
    int*   IDX  = (int*)  symaddr(g_idx);
    float* FEAT = (float*)symaddr(g_feat);
    float* Y1   = (float*)symaddr(g_y1);
    float* Y2   = (float*)symaddr(g_y2);
    float* X1   = (float*)symaddr(g_x1);
    float* X2   = (float*)symaddr(g_x2);
    float* XC   = (float*)symaddr(g_xc);
    float* Y3   = (float*)symaddr(g_y3);
    float* WT   = (float*)symaddr(g_wt);
    float* MEAN = (float*)symaddr(g_mean);
    float* VAR  = (float*)symaddr(g_var);
    float* OUT  = (float*)d_out;

    const int ew = 256;
    #define GS(total) (unsigned)(((total) + ew - 1) / ew)

    auto conv = [&](const float* W, const float* bias, const float* Xin, float* Yout,
                    int O, int C, int M) {
        int ctot = (C + 7) & ~7;
        transw_k<<<GS(ctot * OPAD), ew>>>(W, WT, O, C);
        gemm_db_k<<<dim3(M / 128, (O + 127) / 128, BSZ), 256>>>(
            WT, Xin, bias, Yout, O, C, M, OPAD, 0, (size_t)C * M, (size_t)O * M);
    };

    auto graph_conv_block = [&](const float* xin, int C, int O1, int O2, int p,
                                float* xout, bool frozen_stats) {
        // knn: sq (warp tree), gram, topk
        sqnorm_warp_k<<<(BSZ * NPTS * 32 + 255) / 256, 256>>>(xin, SQ, C);
        gemm_db_k<<<dim3(NPTS / 128, NPTS / 128, BSZ), 256>>>(
            xin, xin, nullptr, G, NPTS, C, NPTS,
            NPTS, (size_t)C * NPTS, (size_t)C * NPTS, (size_t)NPTS * NPTS);
        topk_k<<<dim3(NPTS, BSZ), 256>>>(G, SQ, IDX);
        // edge features
        int twoC = 2 * C;
        gather_k<<<GS((size_t)BSZ * twoC * MBIG), ew>>>(xin, IDX, FEAT, C);
        // conv1 -> stats -> bn+leaky (in place)
        conv(W1(p), B1(p), FEAT, Y1, O1, twoC, MBIG);
        if (frozen_stats) bn_stats_k<<<O1, 256>>>(Y1, MEAN, VAR, O1, MBIG);
        else              bn_stats_fast_k<<<O1, 256>>>(Y1, MEAN, VAR, O1, MBIG);
        bn_leaky_k<<<GS((size_t)BSZ * O1 * MBIG / 4), ew>>>(Y1, MEAN, VAR, G1(p), BE1(p), O1, MBIG);
        // conv2 -> stats -> BN2+leaky+maxk (exact ref order)
        conv(W2(p), B2(p), Y1, Y2, O2, O1, MBIG);
        if (frozen_stats) bn_stats_k<<<O2, 256>>>(Y2, MEAN, VAR, O2, MBIG);
        else              bn_stats_fast_k<<<O2, 256>>>(Y2, MEAN, VAR, O2, MBIG);
        bn_leaky_maxk_k<<<GS((size_t)BSZ * O2 * NPTS), ew>>>(Y2, MEAN, VAR, G2(p), BE2(p), xout, O2);
    };

    // block 1: C=64 -> 152 -> 181, pooled to X1 (x1 feeds knn-2: frozen stats)
    graph_conv_block(x,  64, 152, 181, 0, X1, true);
    // block 2: C=181 -> 430 -> 512, pooled to X2 (tolerance path: fast stats)
    graph_conv_block(X1, 181, 430, 512, 1, X2, false);

    // block 3: concat -> 595 -> 512 (no graph, no pooling; tolerance path)
    concat_k<<<GS((size_t)BSZ * 693 * NPTS), ew>>>(X1, X2, XC);
    conv(W1(2), B1(2), XC, Y3, 595, 693, NPTS);
    bn_stats_fast_k<<<595, 256>>>(Y3, MEAN, VAR, 595, NPTS);
    bn_leaky_k<<<GS((size_t)BSZ * 595 * NPTS / 4), ew>>>(Y3, MEAN, VAR, G1(2), BE1(2), 595, NPTS);
    conv(W2(2), B2(2), Y3, OUT, 512, 595, NPTS);
    bn_stats_fast_k<<<512, 256>>>(OUT, MEAN, VAR, 512, NPTS);
    bn_leaky_k<<<GS((size_t)BSZ * 512 * NPTS / 4), ew>>>(OUT, MEAN, VAR, G2(2), BE2(2), 512, NPTS);
}

// round 8
// speedup vs baseline: 2.2818x; 1.2060x over previous
#include <cuda_runtime.h>
#include <cfloat>
#include <cstdint>

#define BSZ   8
#define NPTS  2048
#define KNN   10
#define MBIG  (NPTS * KNN)   // 20480
#define OPAD  768            // padded O stride for transposed weights
#define CPAD  704            // padded C rows (704 = 44*16, covers 693)
#define KT    16             // GEMM k-tile depth

typedef unsigned long long u64;
union F2U { float2 f2; u64 u; };

// ---------------- scratch (device globals; allocation-free) ----------------
__device__ float g_G   [(size_t)BSZ * NPTS * NPTS];     // gram
__device__ float g_sq  [BSZ * NPTS];
__device__ int   g_idx [BSZ * NPTS * KNN];
__device__ float g_feat[(size_t)BSZ * 362 * MBIG];      // edge features (block 1)
__device__ float g_y1  [(size_t)BSZ * 430 * MBIG];      // conv1 out (max O=430)
__device__ float g_y2  [(size_t)BSZ * 512 * MBIG];      // conv2 out (max O=512)
__device__ float g_x1  [BSZ * 181 * NPTS];
__device__ float g_x2  [BSZ * 512 * NPTS];
__device__ float g_xc  [BSZ * 693 * NPTS];
__device__ float g_y3  [BSZ * 595 * NPTS];
__device__ float g_P   [BSZ * 430 * NPTS];              // split-conv P
__device__ float g_S   [BSZ * 430 * NPTS];              // split-conv S
__device__ float g_wt  [CPAD * OPAD];                   // transposed + padded weights
__device__ float g_mean[1024];
__device__ float g_var [1024];

// ---- squared norms: XLA row-reduction emulation (BIT-FROZEN, feeds knn) ----
__global__ void sqnorm_warp_k(const float* __restrict__ X, float* __restrict__ sq, int C)
{
    int gw   = (blockIdx.x * blockDim.x + threadIdx.x) >> 5;
    int lane = threadIdx.x & 31;
    if (gw >= BSZ * NPTS) return;
    int b = gw / NPTS, n = gw % NPTS;
    const float* Xb = X + (size_t)b * C * NPTS + n;
    float s = 0.f;
    for (int c = lane; c < C; c += 32) {
        float v = Xb[(size_t)c * NPTS];
        s = __fadd_rn(s, __fmul_rn(v, v));
    }
    #pragma unroll
    for (int off = 16; off > 0; off >>= 1)
        s = __fadd_rn(s, __shfl_down_sync(0xffffffffu, s, off));
    if (lane == 0) sq[gw] = s;
}

// --------- W transpose (sub-slice, strided) into padded buffer ----------
// Wt[c][o] = W[o*ldW + coff + c] for c<C, o<O; zero outside (rows to 16-pad).
__global__ void transw_k(const float* __restrict__ W, float* __restrict__ Wt,
                         int O, int C, int ldW, int coff)
{
    int i = blockIdx.x * blockDim.x + threadIdx.x;
    int ctot = (C + KT - 1) & ~(KT - 1);
    if (i >= ctot * OPAD) return;
    int c = i / OPAD, o = i % OPAD;
    Wt[i] = (c < C && o < O) ? W[(size_t)o * ldW + coff + c] : 0.f;
}

// Wt[c][o] = W[o*ldW + coff2 + c] - W[o*ldW + coff1 + c]  (for split S-gemm)
__global__ void transw_diff_k(const float* __restrict__ W, float* __restrict__ Wt,
                              int O, int C, int ldW, int coff1, int coff2)
{
    int i = blockIdx.x * blockDim.x + threadIdx.x;
    int ctot = (C + KT - 1) & ~(KT - 1);
    if (i >= ctot * OPAD) return;
    int c = i / OPAD, o = i % OPAD;
    Wt[i] = (c < C && o < O)
          ? W[(size_t)o * ldW + coff2 + c] - W[(size_t)o * ldW + coff1 + c] : 0.f;
}

// ---------------- cp.async helpers ----------------
__device__ __forceinline__ void cpa16(uint32_t s, const void* g, int sz)
{
    asm volatile("cp.async.cg.shared.global [%0], [%1], 16, %2;"
                 :: "r"(s), "l"(g), "r"(sz));
}
__device__ __forceinline__ void cpa_commit() { asm volatile("cp.async.commit_group;"); }
template<int N> __device__ __forceinline__ void cpa_wait()
{ asm volatile("cp.async.wait_group %0;" :: "n"(N)); }

// packed dual fp32 FMA (each half IEEE RN, same rounding as scalar FFMA)
__device__ __forceinline__ void ffma2(u64& d, u64 a, u64 b)
{
    asm("fma.rn.f32x2 %0, %1, %2, %0;" : "+l"(d) : "l"(a), "l"(b));
}
__device__ __forceinline__ u64 packdup(float a)
{
    u64 r;
    asm("mov.b64 %0, {%1, %1};" : "=l"(r) : "f"(a));
    return r;
}

// ------- double-buffered 128x128xKT SIMT sgemm, FFMA2 inner ------------------
// Per-output accumulation: single register chain, fmaf, strictly ascending c
// (bit-identical to rounds 4/6/7 passing gemms; pad rows are exact no-ops).
__global__ __launch_bounds__(256, 2) void gemm_db_k(
    const float* __restrict__ A, const float* __restrict__ X,
    const float* __restrict__ bias, float* __restrict__ Y,
    int O, int C, int M, int ldA, size_t sA, size_t sX, size_t sY)
{
    const int b = blockIdx.z;
    const float* Ab = A + (size_t)b * sA;
    const float* Xb = X + (size_t)b * sX;
    float* Yb = Y + (size_t)b * sY;
    const int m0 = blockIdx.x * 128;
    const int o0 = blockIdx.y * 128;
    const int tid = threadIdx.x;
    const int tx = tid & 15, ty = tid >> 4;

    __shared__ float As[2][KT][128];
    __shared__ float Bs[2][KT][128];

    const int rr = tid >> 4;          // 0..15: k-row this thread fills
    const int cl = (tid & 15) * 8;    // 0,8,...,120: two float4 chunks

    uint32_t saA = (uint32_t)__cvta_generic_to_shared(&As[0][rr][cl]);
    uint32_t saB = (uint32_t)__cvta_generic_to_shared(&Bs[0][rr][cl]);
    const uint32_t bufoff = KT * 128 * 4;

    const int ntiles = (C + KT - 1) / KT;

    u64 acc2[2][2][4][2];
    #pragma unroll
    for (int rh = 0; rh < 2; rh++)
        #pragma unroll
        for (int ch = 0; ch < 2; ch++)
            #pragma unroll
            for (int i = 0; i < 4; i++)
                { acc2[rh][ch][i][0] = 0ull; acc2[rh][ch][i][1] = 0ull; }

    // prefetch tile 0
    {
        int c = rr;
        int pz = (c < C) ? 16 : 0;
        int cs = (c < C) ? c : 0;
        const float* ga = Ab + (size_t)cs * ldA + o0 + cl;
        const float* gx = Xb + (size_t)cs * M + m0 + cl;
        cpa16(saA,      ga,     pz);
        cpa16(saA + 16, ga + 4, pz);
        cpa16(saB,      gx,     pz);
        cpa16(saB + 16, gx + 4, pz);
        cpa_commit();
    }

    for (int it = 0; it < ntiles; it++) {
        int buf = it & 1;
        if (it + 1 < ntiles) {
            int c = (it + 1) * KT + rr;
            int pz = (c < C) ? 16 : 0;
            int cs = (c < C) ? c : 0;
            uint32_t nb = ((it + 1) & 1) * bufoff;
            const float* ga = Ab + (size_t)cs * ldA + o0 + cl;
            const float* gx = Xb + (size_t)cs * M + m0 + cl;
            cpa16(saA + nb,      ga,     pz);
            cpa16(saA + nb + 16, ga + 4, pz);
            cpa16(saB + nb,      gx,     pz);
            cpa16(saB + nb + 16, gx + 4, pz);
            cpa_commit();
            cpa_wait<1>();
        } else {
            cpa_wait<0>();
        }
        __syncthreads();
        #pragma unroll
        for (int k = 0; k < KT; k++) {
            float a[2][4];
            *(float4*)a[0] = *(const float4*)&As[buf][k][ty * 4];
            *(float4*)a[1] = *(const float4*)&As[buf][k][64 + ty * 4];
            u64 x0[2], x1[2];
            {
                ulonglong2 v = *(const ulonglong2*)&Bs[buf][k][tx * 4];
                x0[0] = v.x; x0[1] = v.y;
            }
            {
                ulonglong2 v = *(const ulonglong2*)&Bs[buf][k][64 + tx * 4];
                x1[0] = v.x; x1[1] = v.y;
            }
            #pragma unroll
            for (int rh = 0; rh < 2; rh++)
                #pragma unroll
                for (int i = 0; i < 4; i++) {
                    u64 aa = packdup(a[rh][i]);
                    ffma2(acc2[rh][0][i][0], aa, x0[0]);
                    ffma2(acc2[rh][0][i][1], aa, x0[1]);
                    ffma2(acc2[rh][1][i][0], aa, x1[0]);
                    ffma2(acc2[rh][1][i][1], aa, x1[1]);
                }
        }
        __syncthreads();
    }

    #pragma unroll
    for (int rh = 0; rh < 2; rh++)
        #pragma unroll
        for (int i = 0; i < 4; i++) {
            int o = o0 + rh * 64 + ty * 4 + i;
            if (o < O) {
                #pragma unroll
                for (int ch = 0; ch < 2; ch++) {
                    F2U q0, q1;
                    q0.u = acc2[rh][ch][i][0];
                    q1.u = acc2[rh][ch][i][1];
                    float4 r;
                    if (bias) {
                        float bv = bias[o];
                        r.x = q0.f2.x + bv; r.y = q0.f2.y + bv;
                        r.z = q1.f2.x + bv; r.w = q1.f2.y + bv;
                    } else {
                        r.x = q0.f2.x; r.y = q0.f2.y;
                        r.z = q1.f2.x; r.w = q1.f2.y;
                    }
                    *(float4*)&Yb[(size_t)o * M + m0 + ch * 64 + tx * 4] = r;
                }
            }
        }
}

// ------- top-10: register-resident keys (selection semantics = frozen) -------
__global__ void topk_k(const float* __restrict__ G, const float* __restrict__ sq,
                       int* __restrict__ idx)
{
    const int n = blockIdx.x, b = blockIdx.y;
    const float* Gr  = G + ((size_t)b * NPTS + n) * NPTS;
    const float* sqb = sq + b * NPTS;
    const int t = threadIdx.x;
    const int lane = t & 31, warp = t >> 5;
    const float sqn = sqb[n];

    float key[8];
    #pragma unroll
    for (int s = 0; s < 8; s++) {
        int j = s * 256 + t;
        key[s] = (j == n) ? FLT_MAX
               : __fadd_rn(__fadd_rn(__fmul_rn(-2.f, Gr[j]), sqb[j]), sqn);
    }

    __shared__ float swv[8];
    __shared__ int   swi[8];
    __shared__ int   win;

    for (int r = 0; r < KNN; r++) {
        float bv = key[0]; int bs = 0;
        #pragma unroll
        for (int s = 1; s < 8; s++)
            if (key[s] < bv) { bv = key[s]; bs = s; }
        int bj = bs * 256 + t;
        #pragma unroll
        for (int off = 16; off > 0; off >>= 1) {
            float ov = __shfl_down_sync(0xffffffffu, bv, off);
            int   oj = __shfl_down_sync(0xffffffffu, bj, off);
            if (ov < bv || (ov == bv && oj < bj)) { bv = ov; bj = oj; }
        }
        if (lane == 0) { swv[warp] = bv; swi[warp] = bj; }
        __syncthreads();
        if (t == 0) {
            float fv = swv[0]; int fj = swi[0];
            #pragma unroll
            for (int w = 1; w < 8; w++)
                if (swv[w] < fv || (swv[w] == fv && swi[w] < fj)) { fv = swv[w]; fj = swi[w]; }
            idx[((size_t)b * NPTS + n) * KNN + r] = fj;
            win = fj;
        }
        __syncthreads();
        int fj = win;
        if ((fj & 255) == t) key[fj >> 8] = FLT_MAX;
        __syncthreads();
    }
}

// ---------------- gather edge features (block 1 only, FROZEN path) ----------
__global__ void gather_k(const float* __restrict__ X, const int* __restrict__ idx,
                         float* __restrict__ F, int C)
{
    size_t total = (size_t)BSZ * 2 * C * MBIG;
    size_t i = (size_t)blockIdx.x * blockDim.x + threadIdx.x;
    if (i >= total) return;
    int m = (int)(i % MBIG);
    size_t r = i / MBIG;
    int c = (int)(r % (2 * C));
    int b = (int)(r / (2 * C));
    int n = m / KNN, k = m % KNN;
    if (c < C) {
        int j = idx[((size_t)b * NPTS + n) * KNN + k];
        const float* row = X + ((size_t)b * C + c) * NPTS;
        F[i] = row[j] - row[n];
    } else {
        F[i] = X[((size_t)b * C + (c - C)) * NPTS + n];
    }
}

// -------- split-conv combine: Y1[b][o][m] = P[b][o][idx[b][m]] + S[b][o][m/K] -
__global__ void combine_split_k(const float* __restrict__ P, const float* __restrict__ S,
                                const int* __restrict__ idx, float* __restrict__ Y, int O)
{
    size_t total = (size_t)BSZ * O * MBIG;
    size_t i = (size_t)blockIdx.x * blockDim.x + threadIdx.x;
    if (i >= total) return;
    int m = (int)(i % MBIG);
    size_t r = i / MBIG;
    int o = (int)(r % O);
    int b = (int)(r / O);
    int n = m / KNN;
    int j = idx[(size_t)b * MBIG + m];
    size_t base = ((size_t)b * O + o) * NPTS;
    Y[i] = P[base + j] + S[base + n];
}

// ------- BN statistics, two-pass (BIT-FROZEN: block-1 stats feed knn-2) ------
__global__ void bn_stats_k(const float* __restrict__ Y, float* __restrict__ mean,
                           float* __restrict__ var, int O, int M)
{
    const int c = blockIdx.x;
    const int t = threadIdx.x;
    __shared__ float ss[256];
    __shared__ float mu_s;
    float s = 0.f;
    for (int b = 0; b < BSZ; b++) {
        const float* p = Y + ((size_t)b * O + c) * M;
        for (int m = t; m < M; m += 256) s += p[m];
    }
    ss[t] = s;
    __syncthreads();
    for (int w = 128; w > 0; w >>= 1) {
        if (t < w) ss[t] += ss[t + w];
        __syncthreads();
    }
    if (t == 0) {
        float mu = ss[0] / ((float)BSZ * (float)M);
        mean[c] = mu;
        mu_s = mu;
    }
    __syncthreads();
    const float mu = mu_s;
    float s2 = 0.f;
    for (int b = 0; b < BSZ; b++) {
        const float* p = Y + ((size_t)b * O + c) * M;
        for (int m = t; m < M; m += 256) { float d = p[m] - mu; s2 += d * d; }
    }
    ss[t] = s2;
    __syncthreads();
    for (int w = 128; w > 0; w >>= 1) {
        if (t < w) ss[t] += ss[t + w];
        __syncthreads();
    }
    if (t == 0) var[c] = ss[0] / ((float)BSZ * (float)M);
}

// ------- BN statistics, single-pass (tolerance paths: blocks 2 & 3) ----------
__global__ void bn_stats_fast_k(const float* __restrict__ Y, float* __restrict__ mean,
                                float* __restrict__ var, int O, int M)
{
    const int c = blockIdx.x;
    const int t = threadIdx.x;
    __shared__ float ss[256], ss2[256];
    float s = 0.f, s2 = 0.f;
    for (int b = 0; b < BSZ; b++) {
        const float* p = Y + ((size_t)b * O + c) * M;
        for (int m = t * 4; m < M; m += 1024) {
            float4 v = *(const float4*)(p + m);
            s += v.x; s2 = fmaf(v.x, v.x, s2);
            s += v.y; s2 = fmaf(v.y, v.y, s2);
            s += v.z; s2 = fmaf(v.z, v.z, s2);
            s += v.w; s2 = fmaf(v.w, v.w, s2);
        }
    }
    ss[t] = s; ss2[t] = s2;
    __syncthreads();
    for (int w = 128; w > 0; w >>= 1) {
        if (t < w) { ss[t] += ss[t + w]; ss2[t] += ss2[t + w]; }
        __syncthreads();
    }
    if (t == 0) {
        float inv = 1.f / ((float)BSZ * (float)M);
        float mu  = ss[0] * inv;
        mean[c] = mu;
        var[c]  = fmaxf(ss2[0] * inv - mu * mu, 0.f);
    }
}

// -------- apply BN affine + leaky relu, in place ----
__global__ void bn_leaky_k(float* __restrict__ Y, const float* __restrict__ mean,
                           const float* __restrict__ var, const float* __restrict__ gam,
                           const float* __restrict__ bet, int O, size_t M)
{
    size_t total = (size_t)BSZ * O * M;
    size_t i = ((size_t)blockIdx.x * blockDim.x + threadIdx.x) * 4;
    if (i >= total) return;
    int c = (int)((i / M) % O);
    float a  = rsqrtf(var[c] + 1e-5f) * gam[c];
    float bb = bet[c] - mean[c] * a;
    float4 v = *(float4*)(Y + i);
    float tt;
    tt = fmaf(v.x, a, bb); v.x = (tt >= 0.f) ? tt : 0.2f * tt;
    tt = fmaf(v.y, a, bb); v.y = (tt >= 0.f) ? tt : 0.2f * tt;
    tt = fmaf(v.z, a, bb); v.z = (tt >= 0.f) ? tt : 0.2f * tt;
    tt = fmaf(v.w, a, bb); v.w = (tt >= 0.f) ? tt : 0.2f * tt;
    *(float4*)(Y + i) = v;
}

// ---- BN + leaky + max over K, exact ref op order (BIT-FROZEN) ----
__global__ void bn_leaky_maxk_k(const float* __restrict__ Y, const float* __restrict__ mean,
                                const float* __restrict__ var, const float* __restrict__ gam,
                                const float* __restrict__ bet, float* __restrict__ out, int O)
{
    size_t total = (size_t)BSZ * O * NPTS;
    size_t i = (size_t)blockIdx.x * blockDim.x + threadIdx.x;
    if (i >= total) return;
    int n = (int)(i % NPTS);
    int c = (int)((i / NPTS) % O);
    int b = (int)(i / ((size_t)NPTS * O));
    const float mu = mean[c];
    const float s  = __fsqrt_rn(__fadd_rn(var[c], 1e-5f));
    const float g  = gam[c];
    const float be = bet[c];
    const float* p = Y + ((size_t)b * O + c) * MBIG + (size_t)n * KNN;
    float sel = p[0];
    if (g >= 0.f) {
        #pragma unroll
        for (int k = 1; k < KNN; k++) sel = fmaxf(sel, p[k]);
    } else {
        #pragma unroll
        for (int k = 1; k < KNN; k++) sel = fminf(sel, p[k]);
    }
    float t = __fdiv_rn(__fsub_rn(sel, mu), s);
    t = __fadd_rn(__fmul_rn(t, g), be);
    t = (t >= 0.f) ? t : __fmul_rn(0.2f, t);
    out[i] = t;
}

// ---------------- concat [x1;x2] -> xc [B][693][N] ----------------
__global__ void concat_k(const float* __restrict__ x1, const float* __restrict__ x2,
                         float* __restrict__ xc)
{
    size_t total = (size_t)BSZ * 693 * NPTS;
    size_t i = (size_t)blockIdx.x * blockDim.x + threadIdx.x;
    if (i >= total) return;
    int n = (int)(i % NPTS);
    int c = (int)((i / NPTS) % 693);
    int b = (int)(i / ((size_t)NPTS * 693));
    xc[i] = (c < 181) ? x1[((size_t)b * 181 + c) * NPTS + n]
                      : x2[((size_t)b * 512 + (c - 181)) * NPTS + n];
}

// ============================ host launcher ============================
static inline void* symaddr(const void* sym)
{
    void* p = nullptr;
    cudaGetSymbolAddress(&p, sym);
    return p;
}

extern "C" void kernel_launch(void* const* d_in, const int* in_sizes, int n_in,
                              void* d_out, int out_size)
{
    (void)in_sizes; (void)n_in; (void)out_size;
    const float* x = (const float*)d_in[0];

    const float* P24[24];
    for (int i = 0; i < 24; i++) P24[i] = (const float*)d_in[1 + i];
    #define W1(p)  P24[(p)*8 + 0]
    #define B1(p)  P24[(p)*8 + 1]
    #define G1(p)  P24[(p)*8 + 2]
    #define BE1(p) P24[(p)*8 + 3]
    #define W2(p)  P24[(p)*8 + 4]
    #define B2(p)  P24[(p)*8 + 5]
    #define G2(p)  P24[(p)*8 + 6]
    #define BE2(p) P24[(p)*8 + 7]

    float* G    = (float*)symaddr(g_G);
    float* SQ   = (float*)symaddr(g_sq);
    int*   IDX  = (int*)  symaddr(g_idx);
    float* FEAT = (float*)symaddr(g_feat);
    float* Y1   = (float*)symaddr(g_y1);
    float* Y2   = (float*)symaddr(g_y2);
    float* X1   = (float*)symaddr(g_x1);
    float* X2   = (float*)symaddr(g_x2);
    float* XC   = (float*)symaddr(g_xc);
    float* Y3   = (float*)symaddr(g_y3);
    float* PP   = (float*)symaddr(g_P);
    float* SS   = (float*)symaddr(g_S);
    float* WT   = (float*)symaddr(g_wt);
    float* MEAN = (float*)symaddr(g_mean);
    float* VAR  = (float*)symaddr(g_var);
    float* OUT  = (float*)d_out;

    const int ew = 256;
    #define GS(total) (unsigned)(((total) + ew - 1) / ew)
    #define CT(C) (((C) + KT - 1) & ~(KT - 1))

    auto conv = [&](const float* W, const float* bias, const float* Xin, float* Yout,
                    int O, int C, int M) {
        transw_k<<<GS(CT(C) * OPAD), ew>>>(W, WT, O, C, C, 0);
        gemm_db_k<<<dim3(M / 128, (O + 127) / 128, BSZ), 256>>>(
            WT, Xin, bias, Yout, O, C, M, OPAD, 0, (size_t)C * M, (size_t)O * M);
    };

    auto knn = [&](const float* xin, int C) {
        sqnorm_warp_k<<<(BSZ * NPTS * 32 + 255) / 256, 256>>>(xin, SQ, C);
        gemm_db_k<<<dim3(NPTS / 128, NPTS / 128, BSZ), 256>>>(
            xin, xin, nullptr, G, NPTS, C, NPTS,
            NPTS, (size_t)C * NPTS, (size_t)C * NPTS, (size_t)NPTS * NPTS);
        topk_k<<<dim3(NPTS, BSZ), 256>>>(G, SQ, IDX);
    };

    // ================= block 1 (FROZEN: produces x1 -> knn-2) =================
    {
        const int C = 64, O1 = 152, O2 = 181;
        knn(x, C);
        gather_k<<<GS((size_t)BSZ * 2 * C * MBIG), ew>>>(x, IDX, FEAT, C);
        conv(W1(0), B1(0), FEAT, Y1, O1, 2 * C, MBIG);
        bn_stats_k<<<O1, 256>>>(Y1, MEAN, VAR, O1, MBIG);
        bn_leaky_k<<<GS((size_t)BSZ * O1 * MBIG / 4), ew>>>(Y1, MEAN, VAR, G1(0), BE1(0), O1, MBIG);
        conv(W2(0), B2(0), Y1, Y2, O2, O1, MBIG);
        bn_stats_k<<<O2, 256>>>(Y2, MEAN, VAR, O2, MBIG);
        bn_leaky_maxk_k<<<GS((size_t)BSZ * O2 * NPTS), ew>>>(Y2, MEAN, VAR, G2(0), BE2(0), X1, O2);
    }

    // ================= block 2 (tolerance path: split conv1) ==================
    {
        const int C = 181, O1 = 430, O2 = 512;
        knn(X1, C);   // knn kernels stay frozen; inputs (x1) unchanged
        // P = W1[:, :C] @ X1        (over N)
        transw_k<<<GS(CT(C) * OPAD), ew>>>(W1(1), WT, O1, C, 2 * C, 0);
        gemm_db_k<<<dim3(NPTS / 128, (O1 + 127) / 128, BSZ), 256>>>(
            WT, X1, nullptr, PP, O1, C, NPTS, OPAD, 0, (size_t)C * NPTS, (size_t)O1 * NPTS);
        // S = (W1[:, C:] - W1[:, :C]) @ X1 + bias   (over N)
        transw_diff_k<<<GS(CT(C) * OPAD), ew>>>(W1(1), WT, O1, C, 2 * C, 0, C);
        gemm_db_k<<<dim3(NPTS / 128, (O1 + 127) / 128, BSZ), 256>>>(
            WT, X1, B1(1), SS, O1, C, NPTS, OPAD, 0, (size_t)C * NPTS, (size_t)O1 * NPTS);
        // Y1[o, n*K+k] = P[o, idx] + S[o, n]
        combine_split_k<<<GS((size_t)BSZ * O1 * MBIG), ew>>>(PP, SS, IDX, Y1, O1);
        bn_stats_fast_k<<<O1, 256>>>(Y1, MEAN, VAR, O1, MBIG);
        bn_leaky_k<<<GS((size_t)BSZ * O1 * MBIG / 4), ew>>>(Y1, MEAN, VAR, G1(1), BE1(1), O1, MBIG);
        conv(W2(1), B2(1), Y1, Y2, O2, O1, MBIG);
        bn_stats_fast_k<<<O2, 256>>>(Y2, MEAN, VAR, O2, MBIG);
        bn_leaky_maxk_k<<<GS((size_t)BSZ * O2 * NPTS), ew>>>(Y2, MEAN, VAR, G2(1), BE2(1), X2, O2);
    }

    // ================= block 3 (tolerance path) ===============================
    concat_k<<<GS((size_t)BSZ * 693 * NPTS), ew>>>(X1, X2, XC);
    conv(W1(2), B1(2), XC, Y3, 595, 693, NPTS);
    bn_stats_fast_k<<<595, 256>>>(Y3, MEAN, VAR, 595, NPTS);
    bn_leaky_k<<<GS((size_t)BSZ * 595 * NPTS / 4), ew>>>(Y3, MEAN, VAR, G1(2), BE1(2), 595, NPTS);
    conv(W2(2), B2(2), Y3, OUT, 512, 595, NPTS);
    bn_stats_fast_k<<<512, 256>>>(OUT, MEAN, VAR, 512, NPTS);
    bn_leaky_k<<<GS((size_t)BSZ * 512 * NPTS / 4), ew>>>(OUT, MEAN, VAR, G2(2), BE2(2), 512, NPTS);
}